// round 2
// baseline (speedup 1.0000x reference)
#include <cuda_runtime.h>
#include <cuda_bf16.h>

// MoEConv: x[32,64,64,64] f32, idx[32] i32, Wc[4,128,64,3,3] f32, bc[4,128] f32
// out[32,128,64,64] f32. Only the selected expert per sample is computed.

#define B_     32
#define IN_C   64
#define OUT_C  128
#define HW     64
#define KK     9          // 3x3
#define CI_T   8          // in-channel chunk
#define XW     68         // padded row width (66 needed: cols -1..64)

__global__ __launch_bounds__(128, 4)
void moe_conv_kernel(const float* __restrict__ x,
                     const int*   __restrict__ idx,
                     const float* __restrict__ Wc,
                     const float* __restrict__ bc,
                     float*       __restrict__ out)
{
    __shared__ float w_s[CI_T * KK * OUT_C];   // [ci][k][co]  36864 B
    __shared__ float x_s[CI_T * 3 * XW];       // [ci][kh][col] 6528 B

    const int h   = blockIdx.x;        // output row
    const int b   = blockIdx.y;        // sample
    const int tid = threadIdx.x;       // 128 threads
    const int pg  = tid & 7;           // pixel group  (8 groups of 8 px)
    const int cg  = tid >> 3;          // chan  group  (16 groups of 8 co)
    const int px0 = pg * 8;
    const int co0 = cg * 8;

    const int e = idx[b];
    const float* Wb = Wc + (size_t)e * OUT_C * IN_C * KK;   // expert weights
    const float* xb = x  + (size_t)b * IN_C * HW * HW;

    float acc[8][8];
    #pragma unroll
    for (int c = 0; c < 8; ++c)
        #pragma unroll
        for (int p = 0; p < 8; ++p) acc[c][p] = 0.f;

    for (int cb = 0; cb < IN_C / CI_T; ++cb) {
        // ---- load weights: Wb[co][ci=cb*8+r/9][k=r%9], 9216 floats.
        // Per co, the 8ci*9k = 72 floats are contiguous -> float4 loads.
        {
            const float* wsrc = Wb + cb * (CI_T * KK);
            for (int i4 = tid; i4 < OUT_C * (CI_T * KK / 4); i4 += 128) {
                int co = i4 / 18;          // 72/4 = 18 float4 per co
                int r  = (i4 - co * 18) * 4;
                float4 v = *reinterpret_cast<const float4*>(wsrc + (size_t)co * (IN_C * KK) + r);
                float tmp[4] = {v.x, v.y, v.z, v.w};
                #pragma unroll
                for (int j = 0; j < 4; ++j) {
                    int rr = r + j;
                    int ci = rr / KK, k = rr - ci * KK;
                    w_s[(ci * KK + k) * OUT_C + co] = tmp[j];
                }
            }
        }
        // ---- load x patch: rows h-1..h+1, cols -1..64, ci chunk
        {
            for (int i = tid; i < CI_T * 3 * 66; i += 128) {
                int ci  = i / (3 * 66);
                int rem = i - ci * (3 * 66);
                int r   = rem / 66;
                int col = rem - r * 66;
                int gr = h + r - 1;
                int gc = col - 1;
                float v = 0.f;
                if ((unsigned)gr < HW && (unsigned)gc < HW)
                    v = xb[((size_t)(cb * CI_T + ci) * HW + gr) * HW + gc];
                x_s[(ci * 3 + r) * XW + col] = v;
            }
        }
        __syncthreads();

        // ---- compute
        #pragma unroll
        for (int ci = 0; ci < CI_T; ++ci) {
            #pragma unroll
            for (int kh = 0; kh < 3; ++kh) {
                float xv[10];
                const float* xrow = &x_s[(ci * 3 + kh) * XW + px0];  // 16B aligned
                #pragma unroll
                for (int j = 0; j < 10; ++j) xv[j] = xrow[j];
                #pragma unroll
                for (int kw = 0; kw < 3; ++kw) {
                    float wv[8];
                    const float* wrow = &w_s[(ci * KK + kh * 3 + kw) * OUT_C + co0];
                    #pragma unroll
                    for (int c = 0; c < 8; ++c) wv[c] = wrow[c];
                    #pragma unroll
                    for (int c = 0; c < 8; ++c)
                        #pragma unroll
                        for (int p = 0; p < 8; ++p)
                            acc[c][p] = fmaf(wv[c], xv[p + kw], acc[c][p]);
                }
            }
        }
        __syncthreads();
    }

    // ---- epilogue: bias + store (float4, px0 is 32B aligned)
    #pragma unroll
    for (int c = 0; c < 8; ++c) {
        float bias = bc[e * OUT_C + co0 + c];
        float* o = out + (((size_t)b * OUT_C + co0 + c) * HW + h) * HW + px0;
        float4 v0 = {acc[c][0] + bias, acc[c][1] + bias, acc[c][2] + bias, acc[c][3] + bias};
        float4 v1 = {acc[c][4] + bias, acc[c][5] + bias, acc[c][6] + bias, acc[c][7] + bias};
        *reinterpret_cast<float4*>(o)     = v0;
        *reinterpret_cast<float4*>(o + 4) = v1;
    }
}

extern "C" void kernel_launch(void* const* d_in, const int* in_sizes, int n_in,
                              void* d_out, int out_size)
{
    const float* x   = (const float*)d_in[0];
    const int*   idx = (const int*)  d_in[1];
    const float* Wc  = (const float*)d_in[2];
    const float* bc  = (const float*)d_in[3];
    float* out = (float*)d_out;

    dim3 grid(HW, B_);   // (h row, sample)
    moe_conv_kernel<<<grid, 128>>>(x, idx, Wc, bc, out);
}

// round 5
// speedup vs baseline: 3.5639x; 3.5639x over previous
#include <cuda_runtime.h>
#include <cuda_bf16.h>
#include <cstdint>

// ============================================================================
// MoEConv implicit GEMM on mma.sync bf16 (hi/lo split, 3 terms, fp32 acc)
// Target is plain sm_103 (no 'a' features): mma.sync/ldmatrix/cp.async only.
// x[32,64,64,64] f32, idx[32] i32, Wc[4,128,64,3,3] f32, bc[4,128] f32
// out[32,128,64,64] f32
// ============================================================================

#define HW_    64
#define B_     32
#define OUT_C  128
#define IN_C   64

// ---- device scratch (allocation-free) ----
__device__ __align__(128) __nv_bfloat16 g_xt_hi[(size_t)B_*HW_*HW_*IN_C]; // [b][h][w][ci]
__device__ __align__(128) __nv_bfloat16 g_xt_lo[(size_t)B_*HW_*HW_*IN_C];
__device__ __align__(128) __nv_bfloat16 g_wt[(size_t)4*9*2*OUT_C*IN_C];   // [e][k][hi/lo][co][ci]

__device__ __forceinline__ uint32_t smem_u32(const void* p) {
    uint32_t a;
    asm("{ .reg .u64 t; cvta.to.shared.u64 t, %1; cvt.u32.u64 %0, t; }" : "=r"(a) : "l"(p));
    return a;
}

#define CP_ASYNC(dst, src, sz) \
    asm volatile("cp.async.cg.shared.global [%0], [%1], 16, %2;" :: "r"(dst), "l"(src), "r"(sz) : "memory")
#define CP_COMMIT() asm volatile("cp.async.commit_group;" ::: "memory")
#define CP_WAIT0()  asm volatile("cp.async.wait_group 0;" ::: "memory")

#define LDSM_X4(r0,r1,r2,r3,a) \
    asm volatile("ldmatrix.sync.aligned.m8n8.x4.shared.b16 {%0,%1,%2,%3},[%4];" \
        : "=r"(r0),"=r"(r1),"=r"(r2),"=r"(r3) : "r"(a))

#define HMMA(c0,c1,c2,c3,a0,a1,a2,a3,b0,b1) \
    asm volatile("mma.sync.aligned.m16n8k16.row.col.f32.bf16.bf16.f32 " \
        "{%0,%1,%2,%3},{%4,%5,%6,%7},{%8,%9},{%0,%1,%2,%3};" \
        : "+f"(c0),"+f"(c1),"+f"(c2),"+f"(c3) \
        : "r"(a0),"r"(a1),"r"(a2),"r"(a3),"r"(b0),"r"(b1))

// ============================================================================
// Kernel 0: weights f32 -> bf16 hi/lo, layout [e][k][term][co][ci]
// ============================================================================
__global__ void prep_w(const float* __restrict__ Wc)
{
    int id = blockIdx.x * 256 + threadIdx.x;            // (e*128+co)*64+ci
    if (id >= 4 * OUT_C * IN_C) return;
    const float* src = Wc + (size_t)id * 9;
    int e   = id >> 13;
    int rem = id & 8191;                                 // co*64+ci
    #pragma unroll
    for (int k = 0; k < 9; ++k) {
        float f = src[k];
        __nv_bfloat16 h = __float2bfloat16(f);
        float r = f - __bfloat162float(h);
        __nv_bfloat16 l = __float2bfloat16(r);
        size_t o = ((size_t)(e * 9 + k) * 2) * 8192 + rem;
        g_wt[o]        = h;
        g_wt[o + 8192] = l;
    }
}

// ============================================================================
// Kernel 1: x [b][ci][h][w] f32 -> Xt [b][h][w][ci] bf16 hi/lo
// ============================================================================
__global__ void prep_x(const float* __restrict__ x)
{
    __shared__ float s[IN_C * 65];
    const int h = blockIdx.x, b = blockIdx.y, t = threadIdx.x;  // 256 threads
    {
        int ci = t >> 2, w4 = t & 3;
        const float* src = x + (((size_t)b * IN_C + ci) * HW_ + h) * HW_;
        #pragma unroll
        for (int q = 0; q < 4; ++q) {
            int w = (w4 + q * 4) * 4;
            float4 v = *(const float4*)(src + w);
            s[ci * 65 + w + 0] = v.x; s[ci * 65 + w + 1] = v.y;
            s[ci * 65 + w + 2] = v.z; s[ci * 65 + w + 3] = v.w;
        }
    }
    __syncthreads();
    {
        int w = t & 63, ci0 = (t >> 6) * 16;
        uint32_t hi[8], lo[8];
        #pragma unroll
        for (int j = 0; j < 8; ++j) {
            float f0 = s[(ci0 + 2*j    ) * 65 + w];
            float f1 = s[(ci0 + 2*j + 1) * 65 + w];
            __nv_bfloat16 h0 = __float2bfloat16(f0), h1 = __float2bfloat16(f1);
            float r0 = f0 - __bfloat162float(h0), r1 = f1 - __bfloat162float(h1);
            __nv_bfloat16 l0 = __float2bfloat16(r0), l1 = __float2bfloat16(r1);
            hi[j] = ((uint32_t)__bfloat16_as_ushort(h1) << 16) | __bfloat16_as_ushort(h0);
            lo[j] = ((uint32_t)__bfloat16_as_ushort(l1) << 16) | __bfloat16_as_ushort(l0);
        }
        size_t base = (((size_t)b * HW_ + h) * HW_ + w) * IN_C + ci0;
        *(uint4*)(g_xt_hi + base)     = make_uint4(hi[0], hi[1], hi[2], hi[3]);
        *(uint4*)(g_xt_hi + base + 8) = make_uint4(hi[4], hi[5], hi[6], hi[7]);
        *(uint4*)(g_xt_lo + base)     = make_uint4(lo[0], lo[1], lo[2], lo[3]);
        *(uint4*)(g_xt_lo + base + 8) = make_uint4(lo[4], lo[5], lo[6], lo[7]);
    }
}

// ============================================================================
// Main kernel: CTA = (4 image rows, sample). 512 threads = 16 warps (8m x 2n).
// Warp tile 32(px) x 64(co). K = 64 per tap, 9 taps, 3 hi/lo terms.
// SMEM: X halo [6][66][72] bf16 hi+lo (once) + W [2 terms][128][72] x2 buf.
// ============================================================================
#define XPITCH  72                       // elems per (ih,wc) row; 144 B
#define XROWB   144
#define XSZ     (6 * 66 * XROWB)         // 57,024 B per term
#define WSZ     (OUT_C * XROWB)          // 18,432 B per term
#define SM_XHI  0
#define SM_XLO  XSZ
#define SM_W    (2 * XSZ)                // two W buffers of 2*WSZ each
#define SMEM_SZ (2 * XSZ + 2 * 2 * WSZ)  // 187,776 B

__device__ __forceinline__ void load_w_tile(uint32_t wbuf_s, int e, int k, int tid)
{
    // 2 terms x 128 co x 8 chunks(16B) = 2048 chunks, 512 threads -> 4 each
    const size_t kbase = (size_t)(e * 9 + k) * 2 * 8192;
    #pragma unroll
    for (int q = 0; q < 4; ++q) {
        int c    = tid + q * 512;
        int term = c >> 10;
        int rem  = c & 1023;
        int co   = rem >> 3, ch = rem & 7;
        const char* src = (const char*)(g_wt + kbase + (size_t)term * 8192 + co * 64 + ch * 8);
        uint32_t dst = wbuf_s + term * WSZ + co * XROWB + ch * 16;
        CP_ASYNC(dst, src, 16);
    }
}

__global__ __launch_bounds__(512, 1)
void moe_conv_mma(const int* __restrict__ idx, const float* __restrict__ bc,
                  float* __restrict__ out)
{
    extern __shared__ __align__(128) char smem[];
    const uint32_t sb = smem_u32(smem);

    const int g = blockIdx.x, b = blockIdx.y;      // g: 4-row group (0..15)
    const int tid = threadIdx.x;
    const int wid = tid >> 5, lane = tid & 31;
    const int mw = wid & 7, nw = wid >> 3;         // warp grid 8(m) x 2(n)
    const int h0 = g * 4;
    const int e  = idx[b];

    // ---- lane-invariant ldmatrix addressing ----
    const int row16 = (lane & 7) | ((lane >> 3) & 1) << 3;  // 0..15
    const int khalf = lane >> 4;                            // 0/1 (k 0-7 / 8-15)
    const int px0   = mw * 32 + row16;                      // mtile 0 pixel
    const uint32_t boff0 = (uint32_t)(nw * 64 + row16) * XROWB + khalf * 16;

    // ---- start X halo fill + W[0] fill (one cp.async group) ----
    {
        const size_t xb = ((size_t)b * HW_ * HW_) * IN_C;
        for (int c = tid; c < 396 * 8; c += 512) {
            int row = c >> 3, ch = c & 7;
            int ih = row / 66, wc = row - ih * 66;
            int gh = h0 + ih - 1, gw = wc - 1;
            int ok = ((unsigned)gh < HW_ && (unsigned)gw < HW_) ? 16 : 0;
            size_t gi = xb + ((size_t)(ok ? gh : 0) * HW_ + (ok ? gw : 0)) * IN_C + ch * 8;
            uint32_t d = (uint32_t)(row * XROWB + ch * 16);
            CP_ASYNC(sb + SM_XHI + d, (const char*)(g_xt_hi + gi), ok);
            CP_ASYNC(sb + SM_XLO + d, (const char*)(g_xt_lo + gi), ok);
        }
        load_w_tile(sb + SM_W, e, 0, tid);
        CP_COMMIT();
    }

    float acc[2][8][4];
    #pragma unroll
    for (int m = 0; m < 2; ++m)
        #pragma unroll
        for (int n = 0; n < 8; ++n)
            #pragma unroll
            for (int j = 0; j < 4; ++j) acc[m][n][j] = 0.f;

    for (int k = 0; k < 9; ++k) {
        const int kh = k / 3, kw = k - kh * 3;
        const uint32_t wbuf = sb + SM_W + (k & 1) * (2 * WSZ);

        CP_WAIT0();
        __syncthreads();
        if (k < 8) { load_w_tile(sb + SM_W + ((k + 1) & 1) * (2 * WSZ), e, k + 1, tid); CP_COMMIT(); }

        // A row offsets for this tap (per mtile)
        uint32_t aoff[2];
        #pragma unroll
        for (int mt = 0; mt < 2; ++mt) {
            int px = px0 + mt * 16;
            int ih = (px >> 6) + kh, wc = (px & 63) + kw;
            aoff[mt] = (uint32_t)(ih * 66 + wc) * XROWB + khalf * 16;
        }

        #pragma unroll
        for (int kc = 0; kc < 4; ++kc) {
            const uint32_t kcb = kc * 32;
            uint32_t ah[2][4], al[2][4], bb[4][4];
            #pragma unroll
            for (int mt = 0; mt < 2; ++mt) {
                LDSM_X4(ah[mt][0], ah[mt][1], ah[mt][2], ah[mt][3], sb + SM_XHI + aoff[mt] + kcb);
                LDSM_X4(al[mt][0], al[mt][1], al[mt][2], al[mt][3], sb + SM_XLO + aoff[mt] + kcb);
            }
            // B hi
            #pragma unroll
            for (int t = 0; t < 4; ++t)
                LDSM_X4(bb[t][0], bb[t][1], bb[t][2], bb[t][3], wbuf + boff0 + t * (16 * XROWB) + kcb);
            #pragma unroll
            for (int mt = 0; mt < 2; ++mt)
                #pragma unroll
                for (int n = 0; n < 8; ++n) {
                    HMMA(acc[mt][n][0], acc[mt][n][1], acc[mt][n][2], acc[mt][n][3],
                         ah[mt][0], ah[mt][1], ah[mt][2], ah[mt][3],
                         bb[n >> 1][n & 1], bb[n >> 1][2 + (n & 1)]);
                    HMMA(acc[mt][n][0], acc[mt][n][1], acc[mt][n][2], acc[mt][n][3],
                         al[mt][0], al[mt][1], al[mt][2], al[mt][3],
                         bb[n >> 1][n & 1], bb[n >> 1][2 + (n & 1)]);
                }
            // B lo (reuse regs)
            #pragma unroll
            for (int t = 0; t < 4; ++t)
                LDSM_X4(bb[t][0], bb[t][1], bb[t][2], bb[t][3], wbuf + WSZ + boff0 + t * (16 * XROWB) + kcb);
            #pragma unroll
            for (int mt = 0; mt < 2; ++mt)
                #pragma unroll
                for (int n = 0; n < 8; ++n)
                    HMMA(acc[mt][n][0], acc[mt][n][1], acc[mt][n][2], acc[mt][n][3],
                         ah[mt][0], ah[mt][1], ah[mt][2], ah[mt][3],
                         bb[n >> 1][n & 1], bb[n >> 1][2 + (n & 1)]);
        }
        __syncthreads();   // all warps done with wbuf before it is refilled next+1
    }

    // ---- epilogue: direct STG (each warp-quad writes full 32B sectors) ----
    const int grp = lane >> 2, qid = lane & 3;
    const size_t ob = (size_t)b * OUT_C * (HW_ * HW_) + h0 * HW_;
    #pragma unroll
    for (int mt = 0; mt < 2; ++mt) {
        int pxa = mw * 32 + mt * 16 + grp;
        #pragma unroll
        for (int n = 0; n < 8; ++n) {
            int co = nw * 64 + n * 8 + qid * 2;
            float b0 = __ldg(bc + e * OUT_C + co);
            float b1 = __ldg(bc + e * OUT_C + co + 1);
            float* o0 = out + ob + (size_t)co * (HW_ * HW_);
            float* o1 = o0 + (HW_ * HW_);
            o0[pxa]     = acc[mt][n][0] + b0;
            o1[pxa]     = acc[mt][n][1] + b1;
            o0[pxa + 8] = acc[mt][n][2] + b0;
            o1[pxa + 8] = acc[mt][n][3] + b1;
        }
    }
}

// ============================================================================
extern "C" void kernel_launch(void* const* d_in, const int* in_sizes, int n_in,
                              void* d_out, int out_size)
{
    const float* x   = (const float*)d_in[0];
    const int*   idx = (const int*)  d_in[1];
    const float* Wc  = (const float*)d_in[2];
    const float* bc  = (const float*)d_in[3];
    float* out = (float*)d_out;

    static bool attr_done = false;
    if (!attr_done) {
        cudaFuncSetAttribute(moe_conv_mma, cudaFuncAttributeMaxDynamicSharedMemorySize, SMEM_SZ);
        attr_done = true;
    }

    prep_w<<<(4 * OUT_C * IN_C + 255) / 256, 256>>>(Wc);
    prep_x<<<dim3(HW_, B_), 256>>>(x);
    moe_conv_mma<<<dim3(16, B_), 512, SMEM_SZ>>>(idx, bc, out);
}

// round 7
// speedup vs baseline: 7.9328x; 2.2259x over previous
#include <cuda_runtime.h>
#include <cuda_fp16.h>
#include <cstdint>

// ============================================================================
// MoEConv implicit GEMM on mma.sync fp16 (single term, fp32 acc)
// Target is plain sm_103 (no 'a' features): mma.sync/ldmatrix/cp.async only.
// x[32,64,64,64] f32, idx[32] i32, Wc[4,128,64,3,3] f32, bc[4,128] f32
// out[32,128,64,64] f32
// fp16 error model: ~1.4e-4 per factor, incoherent over K=576 -> ~2-3e-4 agg.
// ============================================================================

#define HW_    64
#define B_     32
#define OUT_C  128
#define IN_C   64

// ---- device scratch (allocation-free) ----
__device__ __align__(128) __half g_xt[(size_t)B_*HW_*HW_*IN_C];  // [b][h][w][ci]
__device__ __align__(128) __half g_wt[(size_t)4*9*OUT_C*IN_C];   // [e][k][co][ci]

__device__ __forceinline__ uint32_t smem_u32(const void* p) {
    uint32_t a;
    asm("{ .reg .u64 t; cvta.to.shared.u64 t, %1; cvt.u32.u64 %0, t; }" : "=r"(a) : "l"(p));
    return a;
}

#define CP_ASYNC(dst, src, sz) \
    asm volatile("cp.async.cg.shared.global [%0], [%1], 16, %2;" :: "r"(dst), "l"(src), "r"(sz) : "memory")
#define CP_COMMIT() asm volatile("cp.async.commit_group;" ::: "memory")
#define CP_WAIT0()  asm volatile("cp.async.wait_group 0;" ::: "memory")

#define LDSM_X4(r0,r1,r2,r3,a) \
    asm volatile("ldmatrix.sync.aligned.m8n8.x4.shared.b16 {%0,%1,%2,%3},[%4];" \
        : "=r"(r0),"=r"(r1),"=r"(r2),"=r"(r3) : "r"(a))

#define HMMA(c0,c1,c2,c3,a0,a1,a2,a3,b0,b1) \
    asm volatile("mma.sync.aligned.m16n8k16.row.col.f32.f16.f16.f32 " \
        "{%0,%1,%2,%3},{%4,%5,%6,%7},{%8,%9},{%0,%1,%2,%3};" \
        : "+f"(c0),"+f"(c1),"+f"(c2),"+f"(c3) \
        : "r"(a0),"r"(a1),"r"(a2),"r"(a3),"r"(b0),"r"(b1))

// ============================================================================
// Kernel 0: weights f32 -> fp16, layout [e][k][co][ci]
// ============================================================================
__global__ void prep_w(const float* __restrict__ Wc)
{
    int id = blockIdx.x * 256 + threadIdx.x;            // (e*128+co)*64+ci
    if (id >= 4 * OUT_C * IN_C) return;
    const float* src = Wc + (size_t)id * 9;
    int e   = id >> 13;
    int rem = id & 8191;                                 // co*64+ci
    #pragma unroll
    for (int k = 0; k < 9; ++k)
        g_wt[(size_t)(e * 9 + k) * 8192 + rem] = __float2half_rn(src[k]);
}

// ============================================================================
// Kernel 1: x [b][ci][h][w] f32 -> Xt [b][h][w][ci] fp16
// ============================================================================
__global__ void prep_x(const float* __restrict__ x)
{
    __shared__ float s[IN_C * 65];
    const int h = blockIdx.x, b = blockIdx.y, t = threadIdx.x;  // 256 threads
    {
        int ci = t >> 2, w4 = t & 3;
        const float* src = x + (((size_t)b * IN_C + ci) * HW_ + h) * HW_;
        #pragma unroll
        for (int q = 0; q < 4; ++q) {
            int w = (w4 + q * 4) * 4;
            float4 v = *(const float4*)(src + w);
            s[ci * 65 + w + 0] = v.x; s[ci * 65 + w + 1] = v.y;
            s[ci * 65 + w + 2] = v.z; s[ci * 65 + w + 3] = v.w;
        }
    }
    __syncthreads();
    {
        int w = t & 63, ci0 = (t >> 6) * 16;
        uint32_t pk[8];
        #pragma unroll
        for (int j = 0; j < 8; ++j) {
            __half h0 = __float2half_rn(s[(ci0 + 2*j    ) * 65 + w]);
            __half h1 = __float2half_rn(s[(ci0 + 2*j + 1) * 65 + w]);
            pk[j] = ((uint32_t)__half_as_ushort(h1) << 16) | __half_as_ushort(h0);
        }
        size_t base = (((size_t)b * HW_ + h) * HW_ + w) * IN_C + ci0;
        *(uint4*)(g_xt + base)     = make_uint4(pk[0], pk[1], pk[2], pk[3]);
        *(uint4*)(g_xt + base + 8) = make_uint4(pk[4], pk[5], pk[6], pk[7]);
    }
}

// ============================================================================
// Main kernel: CTA = (4 image rows, sample). 512 threads = 16 warps (8m x 2n).
// Warp tile 32(px) x 64(co). K = 64 per tap, 9 taps, single fp16 term.
// SMEM: X halo [6 rows][66 cols][72 pitch] fp16 (once) + W [128co][72] x2 buf.
// ============================================================================
#define XPITCH  72                       // elems per (ih,wc) row; 144 B
#define XROWB   144
#define XSZ     (6 * 66 * XROWB)         // 57,024 B
#define WSZ     (OUT_C * XROWB)          // 18,432 B
#define SM_X    0
#define SM_W    XSZ
#define SMEM_SZ (XSZ + 2 * WSZ)          // 93,888 B

__device__ __forceinline__ void load_w_tile(uint32_t wbuf_s, int e, int k, int tid)
{
    // 128 co x 8 chunks(16B) = 1024 chunks, 512 threads -> 2 each
    const size_t kbase = (size_t)(e * 9 + k) * 8192;
    #pragma unroll
    for (int q = 0; q < 2; ++q) {
        int c  = tid + q * 512;
        int co = c >> 3, ch = c & 7;
        const char* src = (const char*)(g_wt + kbase + co * 64 + ch * 8);
        uint32_t dst = wbuf_s + co * XROWB + ch * 16;
        CP_ASYNC(dst, src, 16);
    }
}

__global__ __launch_bounds__(512, 1)
void moe_conv_mma(const int* __restrict__ idx, const float* __restrict__ bc,
                  float* __restrict__ out)
{
    extern __shared__ __align__(128) char smem[];
    const uint32_t sb = smem_u32(smem);

    const int g = blockIdx.x, b = blockIdx.y;      // g: 4-row group (0..15)
    const int tid = threadIdx.x;
    const int wid = tid >> 5, lane = tid & 31;
    const int mw = wid & 7, nw = wid >> 3;         // warp grid 8(m) x 2(n)
    const int h0 = g * 4;
    const int e  = idx[b];

    // ---- lane-invariant ldmatrix addressing ----
    const int row16 = (lane & 7) | ((lane >> 3) & 1) << 3;  // 0..15
    const int khalf = lane >> 4;                            // 0/1 (k 0-7 / 8-15)
    const int px0   = mw * 32 + row16;                      // mtile 0 pixel
    const uint32_t boff0 = (uint32_t)(nw * 64 + row16) * XROWB + khalf * 16;

    // ---- start X halo fill + W[0] fill (one cp.async group) ----
    {
        const size_t xb = ((size_t)b * HW_ * HW_) * IN_C;
        for (int c = tid; c < 396 * 8; c += 512) {
            int row = c >> 3, ch = c & 7;
            int ih = row / 66, wc = row - ih * 66;
            int gh = h0 + ih - 1, gw = wc - 1;
            int ok = ((unsigned)gh < HW_ && (unsigned)gw < HW_) ? 16 : 0;
            size_t gi = xb + ((size_t)(ok ? gh : 0) * HW_ + (ok ? gw : 0)) * IN_C + ch * 8;
            uint32_t d = (uint32_t)(row * XROWB + ch * 16);
            CP_ASYNC(sb + SM_X + d, (const char*)(g_xt + gi), ok);
        }
        load_w_tile(sb + SM_W, e, 0, tid);
        CP_COMMIT();
    }

    float acc[2][8][4];
    #pragma unroll
    for (int m = 0; m < 2; ++m)
        #pragma unroll
        for (int n = 0; n < 8; ++n)
            #pragma unroll
            for (int j = 0; j < 4; ++j) acc[m][n][j] = 0.f;

    for (int k = 0; k < 9; ++k) {
        const int kh = k / 3, kw = k - kh * 3;
        const uint32_t wbuf = sb + SM_W + (k & 1) * WSZ;

        CP_WAIT0();
        __syncthreads();
        if (k < 8) { load_w_tile(sb + SM_W + ((k + 1) & 1) * WSZ, e, k + 1, tid); CP_COMMIT(); }

        // A row offsets for this tap (per mtile)
        uint32_t aoff[2];
        #pragma unroll
        for (int mt = 0; mt < 2; ++mt) {
            int px = px0 + mt * 16;
            int ih = (px >> 6) + kh, wc = (px & 63) + kw;
            aoff[mt] = (uint32_t)(ih * 66 + wc) * XROWB + khalf * 16;
        }

        #pragma unroll
        for (int kc = 0; kc < 4; ++kc) {
            const uint32_t kcb = kc * 32;
            uint32_t aa[2][4], bb[4][4];
            #pragma unroll
            for (int mt = 0; mt < 2; ++mt)
                LDSM_X4(aa[mt][0], aa[mt][1], aa[mt][2], aa[mt][3], sb + SM_X + aoff[mt] + kcb);
            #pragma unroll
            for (int t = 0; t < 4; ++t)
                LDSM_X4(bb[t][0], bb[t][1], bb[t][2], bb[t][3], wbuf + boff0 + t * (16 * XROWB) + kcb);
            #pragma unroll
            for (int mt = 0; mt < 2; ++mt)
                #pragma unroll
                for (int n = 0; n < 8; ++n)
                    HMMA(acc[mt][n][0], acc[mt][n][1], acc[mt][n][2], acc[mt][n][3],
                         aa[mt][0], aa[mt][1], aa[mt][2], aa[mt][3],
                         bb[n >> 1][n & 1], bb[n >> 1][2 + (n & 1)]);
        }
        __syncthreads();   // all warps done with wbuf before refill lands
    }

    // ---- epilogue: direct STG (each warp-quad writes full 32B sectors) ----
    const int grp = lane >> 2, qid = lane & 3;
    const size_t ob = (size_t)b * OUT_C * (HW_ * HW_) + h0 * HW_;
    #pragma unroll
    for (int mt = 0; mt < 2; ++mt) {
        int pxa = mw * 32 + mt * 16 + grp;
        #pragma unroll
        for (int n = 0; n < 8; ++n) {
            int co = nw * 64 + n * 8 + qid * 2;
            float b0 = __ldg(bc + e * OUT_C + co);
            float b1 = __ldg(bc + e * OUT_C + co + 1);
            float* o0 = out + ob + (size_t)co * (HW_ * HW_);
            float* o1 = o0 + (HW_ * HW_);
            o0[pxa]     = acc[mt][n][0] + b0;
            o1[pxa]     = acc[mt][n][1] + b1;
            o0[pxa + 8] = acc[mt][n][2] + b0;
            o1[pxa + 8] = acc[mt][n][3] + b1;
        }
    }
}

// ============================================================================
extern "C" void kernel_launch(void* const* d_in, const int* in_sizes, int n_in,
                              void* d_out, int out_size)
{
    const float* x   = (const float*)d_in[0];
    const int*   idx = (const int*)  d_in[1];
    const float* Wc  = (const float*)d_in[2];
    const float* bc  = (const float*)d_in[3];
    float* out = (float*)d_out;

    static bool attr_done = false;
    if (!attr_done) {
        cudaFuncSetAttribute(moe_conv_mma, cudaFuncAttributeMaxDynamicSharedMemorySize, SMEM_SZ);
        attr_done = true;
    }

    prep_w<<<(4 * OUT_C * IN_C + 255) / 256, 256>>>(Wc);
    prep_x<<<dim3(HW_, B_), 256>>>(x);
    moe_conv_mma<<<dim3(16, B_), 512, SMEM_SZ>>>(idx, bc, out);
}